// round 9
// baseline (speedup 1.0000x reference)
#include <cuda_runtime.h>
#include <cuda_bf16.h>
#include <cstdint>

// TensorProductScatter: per-edge e3nn tensor product + scatter-add.
// R5 design: warp owns 32 consecutive edges.
//  - idx/attr loaded cooperatively once (6 wf / 32 edges), broadcast via shfl
//  - x1 gathered in 3 coalesced stride-1 rounds + 9-shfl redistribution
//    (was: 3 stride-3 loads = 9 wavefronts re-touching the same lines)
//  - flush via cp.reduce.async.bulk (TMA engine), double-buffered smem rows
// Per-edge L1tex wavefronts: ~29 -> ~20.

#define MULC 32
#define ROWF 352            // 32 + 96 + 96 + 32 + 96
#define WARPS_PER_BLOCK 8
#define EPW 32              // edges per warp
#define FULLM 0xFFFFFFFFu

__device__ __forceinline__ uint32_t smem_u32(const void* p) {
    uint32_t a;
    asm("{ .reg .u64 t; cvta.to.shared.u64 t, %1; cvt.u32.u64 %0, t; }"
        : "=r"(a) : "l"(p));
    return a;
}

__global__ void tps_zero_kernel(float4* __restrict__ out, int n4) {
    int i = blockIdx.x * blockDim.x + threadIdx.x;
    if (i < n4) out[i] = make_float4(0.f, 0.f, 0.f, 0.f);
}

__global__ __launch_bounds__(WARPS_PER_BLOCK * 32)
void tps_scatter_kernel(const float* __restrict__ x,
                        const float* __restrict__ edge_attr,
                        const float* __restrict__ edge_weight,
                        const int*   __restrict__ edge_dst,
                        const int*   __restrict__ edge_src,
                        float*       __restrict__ out,
                        int E) {
    // Double-buffered staging rows per warp
    __shared__ __align__(16) float sm_o[WARPS_PER_BLOCK][2][ROWF];

    const int wb   = threadIdx.x >> 5;
    const int lane = threadIdx.x & 31;
    const long long ebase =
        ((long long)blockIdx.x * WARPS_PER_BLOCK + wb) * EPW;
    if (ebase >= E) return;

    // Cooperative per-lane edge metadata for this warp's 32 edges
    long long emine = ebase + lane;
    if (emine >= E) emine = E - 1;
    const int   sreg = edge_src[emine];
    const int   dreg = edge_dst[emine];
    const float4 areg = __ldg(reinterpret_cast<const float4*>(edge_attr) + emine);

    const float INV_SQRT3 = 0.5773502691896258f;
    const float INV_SQRT2 = 0.7071067811865476f;

    #pragma unroll 1
    for (int t = 0; t < EPW; t++) {
        const long long e = ebase + t;
        if (e >= E) break;                         // warp-uniform

        // Broadcast this edge's scalars (no L1tex traffic)
        const int   s   = __shfl_sync(FULLM, sreg, t);
        const int   d   = __shfl_sync(FULLM, dreg, t);
        const float a0  = __shfl_sync(FULLM, areg.x, t);
        const float a1x = __shfl_sync(FULLM, areg.y, t);
        const float a1y = __shfl_sync(FULLM, areg.z, t);
        const float a1z = __shfl_sync(FULLM, areg.w, t);

        // x row gather: xs0 coalesced; x1 in 3 coalesced stride-1 rounds
        const float* xrow = x + (long long)s * (4 * MULC);
        const float xs0 = __ldg(xrow + lane);
        const float v0  = __ldg(xrow + MULC + 0 * 32 + lane);   // x1flat[lane]
        const float v1  = __ldg(xrow + MULC + 1 * 32 + lane);   // x1flat[32+lane]
        const float v2  = __ldg(xrow + MULC + 2 * 32 + lane);   // x1flat[64+lane]

        // Streaming weights (read-once)
        const float* wrow = edge_weight + e * (5 * MULC);
        const float w0 = __ldcs(wrow + 0 * MULC + lane);
        const float w1 = __ldcs(wrow + 1 * MULC + lane);
        const float w2 = __ldcs(wrow + 2 * MULC + lane);
        const float w3 = __ldcs(wrow + 3 * MULC + lane);
        const float w4 = __ldcs(wrow + 4 * MULC + lane);

        // Redistribute x1flat -> channel order: lane u needs x1flat[3u+k]
        float x1v[3];
        #pragma unroll
        for (int k = 0; k < 3; k++) {
            const int m    = 3 * lane + k;
            const int src  = m & 31;
            const int slot = m >> 5;
            const float t0 = __shfl_sync(FULLM, v0, src);
            const float t1 = __shfl_sync(FULLM, v1, src);
            const float t2 = __shfl_sync(FULLM, v2, src);
            x1v[k] = (slot == 0) ? t0 : ((slot == 1) ? t1 : t2);
        }
        const float x1a = x1v[0], x1b = x1v[1], x1c = x1v[2];

        // Tensor product
        const float o0  = w0 * xs0 * a0;
        const float w1x = w1 * xs0;
        const float o1x = w1x * a1x, o1y = w1x * a1y, o1z = w1x * a1z;
        const float w2a = w2 * a0;
        const float o2x = w2a * x1a, o2y = w2a * x1b, o2z = w2a * x1c;
        const float dot = x1a * a1x + x1b * a1y + x1c * a1z;
        const float o3  = w3 * dot * INV_SQRT3;
        const float cx  = x1b * a1z - x1c * a1y;
        const float cy  = x1c * a1x - x1a * a1z;
        const float cz  = x1a * a1y - x1b * a1x;
        const float w4s = w4 * INV_SQRT2;
        const float o4x = w4s * cx, o4y = w4s * cy, o4z = w4s * cz;

        // Double-buffered staging: before reusing row p, its TMA read (group
        // issued 2 iterations ago) must be complete -> allow <=1 pending.
        const int p = t & 1;
        if (lane == 0 && t >= 2) {
            asm volatile("cp.async.bulk.wait_group 1;" ::: "memory");
        }
        __syncwarp();

        float* r = sm_o[wb][p];
        r[lane]                = o0;
        r[MULC + 3 * lane + 0] = o1x;
        r[MULC + 3 * lane + 1] = o1y;
        r[MULC + 3 * lane + 2] = o1z;
        r[128  + 3 * lane + 0] = o2x;
        r[128  + 3 * lane + 1] = o2y;
        r[128  + 3 * lane + 2] = o2z;
        r[224  + lane]         = o3;
        r[256  + 3 * lane + 0] = o4x;
        r[256  + 3 * lane + 1] = o4y;
        r[256  + 3 * lane + 2] = o4z;
        __syncwarp();

        if (lane == 0) {
            asm volatile("fence.proxy.async.shared::cta;" ::: "memory");
            float*   gptr  = out + (long long)d * ROWF;
            uint32_t saddr = smem_u32(r);
            asm volatile(
                "cp.reduce.async.bulk.global.shared::cta.bulk_group.add.f32 "
                "[%0], [%1], %2;"
                :: "l"(gptr), "r"(saddr), "r"((int)(ROWF * sizeof(float)))
                : "memory");
            asm volatile("cp.async.bulk.commit_group;" ::: "memory");
        }
    }

    // Drain all pending bulk ops before CTA smem can be retired
    if (lane == 0) {
        asm volatile("cp.async.bulk.wait_group 0;" ::: "memory");
    }
}

extern "C" void kernel_launch(void* const* d_in, const int* in_sizes, int n_in,
                              void* d_out, int out_size) {
    const float* x           = (const float*)d_in[0];
    const float* edge_attr   = (const float*)d_in[1];
    const float* edge_weight = (const float*)d_in[2];
    const int*   edge_dst    = (const int*)d_in[3];
    const int*   edge_src    = (const int*)d_in[4];
    float* out = (float*)d_out;

    const int E = in_sizes[3];

    int n4 = out_size / 4;
    tps_zero_kernel<<<(n4 + 255) / 256, 256>>>((float4*)out, n4);

    const int edges_per_block = WARPS_PER_BLOCK * EPW;
    int blocks = (E + edges_per_block - 1) / edges_per_block;
    tps_scatter_kernel<<<blocks, WARPS_PER_BLOCK * 32>>>(
        x, edge_attr, edge_weight, edge_dst, edge_src, out, E);
}

// round 11
// speedup vs baseline: 1.0665x; 1.0665x over previous
#include <cuda_runtime.h>
#include <cuda_bf16.h>
#include <cstdint>

// TensorProductScatter: per-edge e3nn tensor product + scatter-add.
// R8 (best: warp-per-edge, smem-staged row, TMA cp.reduce.async.bulk flush)
// + L2 eviction-priority hints via the policy-register form (the bare
// .L2::evict_last ld modifier is restricted to 256-bit loads on sm_103).
// DRAM traffic is ~1.06 GB vs ~640 MB compulsory: the out region (70 MB,
// RMW ~16x/line) and x table (25.6 MB) are thrashed by the 512 MB weight
// stream. evict_last pins them (95.6 MB < 126 MB L2).

#define MULC 32
#define ROWF 352            // 32 + 96 + 96 + 32 + 96
#define WARPS_PER_BLOCK 8

__device__ __forceinline__ uint32_t smem_u32(const void* p) {
    uint32_t a;
    asm("{ .reg .u64 t; cvta.to.shared.u64 t, %1; cvt.u32.u64 %0, t; }"
        : "=r"(a) : "l"(p));
    return a;
}

__device__ __forceinline__ uint64_t make_evict_last_policy() {
    uint64_t pol;
    asm("createpolicy.fractional.L2::evict_last.b64 %0, 1.0;" : "=l"(pol));
    return pol;
}

__device__ __forceinline__ float ldg_pol(const float* p, uint64_t pol) {
    float v;
    asm volatile("ld.global.nc.L2::cache_hint.f32 %0, [%1], %2;"
                 : "=f"(v) : "l"(p), "l"(pol));
    return v;
}

__global__ void tps_zero_kernel(float4* __restrict__ out, int n4) {
    int i = blockIdx.x * blockDim.x + threadIdx.x;
    if (i < n4) out[i] = make_float4(0.f, 0.f, 0.f, 0.f);
}

__global__ __launch_bounds__(WARPS_PER_BLOCK * 32)
void tps_scatter_kernel(const float* __restrict__ x,
                        const float* __restrict__ edge_attr,
                        const float* __restrict__ edge_weight,
                        const int*   __restrict__ edge_dst,
                        const int*   __restrict__ edge_src,
                        float*       __restrict__ out,
                        int E) {
    __shared__ __align__(16) float sm_o[WARPS_PER_BLOCK][ROWF];

    const int wb   = threadIdx.x >> 5;
    const int lane = threadIdx.x & 31;
    const long long e = (long long)blockIdx.x * WARPS_PER_BLOCK + wb;
    if (e >= E) return;

    const uint64_t pol = make_evict_last_policy();

    // Uniform (warp-broadcast) loads — read-once, evict-first
    const int s = __ldcs(edge_src + e);
    const int d = __ldcs(edge_dst + e);
    const float4 a = __ldcs(reinterpret_cast<const float4*>(edge_attr) + e);
    const float a0 = a.x, a1x = a.y, a1y = a.z, a1z = a.w;

    // x gather: keep the 25.6 MB table pinned in L2 (evict_last policy)
    const float* xrow = x + (long long)s * (4 * MULC);
    const float xs0 = ldg_pol(xrow + lane, pol);
    const float x1a = ldg_pol(xrow + MULC + 3 * lane + 0, pol);
    const float x1b = ldg_pol(xrow + MULC + 3 * lane + 1, pol);
    const float x1c = ldg_pol(xrow + MULC + 3 * lane + 2, pol);

    // Streaming weights (read-once: evict-first)
    const float* wrow = edge_weight + e * (5 * MULC);
    const float w0 = __ldcs(wrow + 0 * MULC + lane);
    const float w1 = __ldcs(wrow + 1 * MULC + lane);
    const float w2 = __ldcs(wrow + 2 * MULC + lane);
    const float w3 = __ldcs(wrow + 3 * MULC + lane);
    const float w4 = __ldcs(wrow + 4 * MULC + lane);

    const float INV_SQRT3 = 0.5773502691896258f;
    const float INV_SQRT2 = 0.7071067811865476f;

    const float o0  = w0 * xs0 * a0;
    const float w1x = w1 * xs0;
    const float o1x = w1x * a1x, o1y = w1x * a1y, o1z = w1x * a1z;
    const float w2a = w2 * a0;
    const float o2x = w2a * x1a, o2y = w2a * x1b, o2z = w2a * x1c;
    const float dot = x1a * a1x + x1b * a1y + x1c * a1z;
    const float o3  = w3 * dot * INV_SQRT3;
    const float cx  = x1b * a1z - x1c * a1y;
    const float cy  = x1c * a1x - x1a * a1z;
    const float cz  = x1a * a1y - x1b * a1x;
    const float w4s = w4 * INV_SQRT2;
    const float o4x = w4s * cx, o4y = w4s * cy, o4z = w4s * cz;

    // Stage the 352-float row (stride-3: gcd(3,32)=1 -> conflict-free)
    float* r = sm_o[wb];
    r[lane]                = o0;
    r[MULC + 3 * lane + 0] = o1x;
    r[MULC + 3 * lane + 1] = o1y;
    r[MULC + 3 * lane + 2] = o1z;
    r[128  + 3 * lane + 0] = o2x;
    r[128  + 3 * lane + 1] = o2y;
    r[128  + 3 * lane + 2] = o2z;
    r[224  + lane]         = o3;
    r[256  + 3 * lane + 0] = o4x;
    r[256  + 3 * lane + 1] = o4y;
    r[256  + 3 * lane + 2] = o4z;
    __syncwarp();

    // TMA bulk-reduce into out[dst], evict_last policy: the 70 MB output
    // region stays L2-resident across its ~16 RMW hits per line.
    if (lane == 0) {
        asm volatile("fence.proxy.async.shared::cta;" ::: "memory");
        float*   gptr  = out + (long long)d * ROWF;
        uint32_t saddr = smem_u32(r);
        asm volatile(
            "cp.reduce.async.bulk.global.shared::cta.bulk_group.add.f32"
            ".L2::cache_hint [%0], [%1], %2, %3;"
            :: "l"(gptr), "r"(saddr), "r"((int)(ROWF * sizeof(float))), "l"(pol)
            : "memory");
        asm volatile("cp.async.bulk.commit_group;" ::: "memory");
        asm volatile("cp.async.bulk.wait_group 0;" ::: "memory");
    }
}

extern "C" void kernel_launch(void* const* d_in, const int* in_sizes, int n_in,
                              void* d_out, int out_size) {
    const float* x           = (const float*)d_in[0];
    const float* edge_attr   = (const float*)d_in[1];
    const float* edge_weight = (const float*)d_in[2];
    const int*   edge_dst    = (const int*)d_in[3];
    const int*   edge_src    = (const int*)d_in[4];
    float* out = (float*)d_out;

    const int E = in_sizes[3];

    int n4 = out_size / 4;
    tps_zero_kernel<<<(n4 + 255) / 256, 256>>>((float4*)out, n4);

    int blocks = (E + WARPS_PER_BLOCK - 1) / WARPS_PER_BLOCK;
    tps_scatter_kernel<<<blocks, WARPS_PER_BLOCK * 32>>>(
        x, edge_attr, edge_weight, edge_dst, edge_src, out, E);
}